// round 12
// baseline (speedup 1.0000x reference)
#include <cuda_runtime.h>
#include <math.h>

#define N_NODES   100000
#define N_EDGES   50000
#define N_INC     3200000
#define D_IN      128
#define D_HID     32
#define N_CLASSES 40

// ---------------- device scratch (no allocations allowed) ----------------
__device__ int g_ncnt[N_NODES];
__device__ int g_ecnt[N_EDGES];
__device__ int g_noff[N_NODES + 1];
__device__ int g_eoff[N_EDGES + 1];
__device__ int g_ncur[N_NODES];
__device__ int g_ecur[N_EDGES];
__device__ int g_edge_members[N_INC];   // node ids grouped by edge
__device__ int g_node_members[N_INC];   // edge ids grouped by node
__device__ __align__(16) float g_xw1[N_NODES * D_HID];
__device__ __align__(16) float g_efeat[N_EDGES * N_CLASSES];   // reused: stride 32 (L1), 40 (L2)
__device__ __align__(16) float g_h[N_NODES * D_HID];
__device__ __align__(16) float g_hw2[N_NODES * N_CLASSES];

// ---------------- CSR build ----------------
__global__ void k_zero() {
    int i = blockIdx.x * blockDim.x + threadIdx.x;
    if (i < N_NODES) g_ncnt[i] = 0;
    if (i < N_EDGES) g_ecnt[i] = 0;
}

__global__ void k_hist(const int* __restrict__ nidx, const int* __restrict__ eidx) {
    int i = blockIdx.x * blockDim.x + threadIdx.x;
    if (i < N_INC) {
        atomicAdd(&g_ncnt[__ldg(nidx + i)], 1);
        atomicAdd(&g_ecnt[__ldg(eidx + i)], 1);
    }
}

// Exclusive scan with warp-shuffle block scan (2 barriers/tile instead of ~30).
// block 0: node counts -> g_noff + g_ncur;  block 1: edge counts -> g_eoff + g_ecur.
__global__ void k_scan() {
    const int* cnt;
    int* off;
    int* cur;
    int n;
    if (blockIdx.x == 0) { cnt = g_ncnt; off = g_noff; cur = g_ncur; n = N_NODES; }
    else                 { cnt = g_ecnt; off = g_eoff; cur = g_ecur; n = N_EDGES; }

    __shared__ int warp_sums[32];
    int tid = threadIdx.x;
    int lane = tid & 31;
    int wid = tid >> 5;
    int carry = 0;

    for (int base = 0; base < n; base += 1024) {
        int idx = base + tid;
        int v = (idx < n) ? cnt[idx] : 0;

        // inclusive warp scan via shuffles
        int x = v;
#pragma unroll
        for (int d = 1; d < 32; d <<= 1) {
            int t = __shfl_up_sync(0xFFFFFFFFu, x, d);
            if (lane >= d) x += t;
        }
        if (lane == 31) warp_sums[wid] = x;
        __syncthreads();

        if (wid == 0) {
            int s = warp_sums[lane];
#pragma unroll
            for (int d = 1; d < 32; d <<= 1) {
                int t = __shfl_up_sync(0xFFFFFFFFu, s, d);
                if (lane >= d) s += t;
            }
            warp_sums[lane] = s;
        }
        __syncthreads();

        int prefix = (wid > 0) ? warp_sums[wid - 1] : 0;
        int excl = carry + prefix + x - v;   // exclusive scan value for idx
        if (idx < n) {
            off[idx] = excl;
            cur[idx] = excl;                 // fused cursor init
        }
        int total = warp_sums[31];
        __syncthreads();                     // protect warp_sums before next tile
        carry += total;
    }
    if (tid == 0) off[n] = carry;
}

__global__ void k_reorder(const int* __restrict__ nidx, const int* __restrict__ eidx) {
    int i = blockIdx.x * blockDim.x + threadIdx.x;
    if (i >= N_INC) return;
    int v = __ldg(nidx + i);
    int e = __ldg(eidx + i);
    int p = atomicAdd(&g_ecur[e], 1);
    g_edge_members[p] = v;
    int q = atomicAdd(&g_ncur[v], 1);
    g_node_members[q] = e;
}

// ---------------- GEMM1: xw1 = x @ W1  [100000,128]x[128,32] ----------------
// 256 threads, 256 rows/block, thread tile 4 rows x 8 cols.
__global__ void k_gemm1(const float* __restrict__ X, const float* __restrict__ W) {
    __shared__ float xs[256][33];
    __shared__ float ws[32][32];
    int tid = threadIdx.x;
    int row0 = blockIdx.x * 256;
    int tc = tid & 3;     // col group -> cols tc*8..+8
    int tr = tid >> 2;    // row group -> rows tr*4..+4

    float acc[4][8];
#pragma unroll
    for (int i = 0; i < 4; i++)
#pragma unroll
        for (int c = 0; c < 8; c++) acc[i][c] = 0.f;

    for (int kc = 0; kc < 128; kc += 32) {
        for (int s = tid; s < 2048; s += 256) {
            int r = s >> 3, v = s & 7;
            int gr = row0 + r;
            float4 val = make_float4(0.f, 0.f, 0.f, 0.f);
            if (gr < N_NODES) val = *(const float4*)(X + (long)gr * 128 + kc + v * 4);
            xs[r][v * 4 + 0] = val.x;
            xs[r][v * 4 + 1] = val.y;
            xs[r][v * 4 + 2] = val.z;
            xs[r][v * 4 + 3] = val.w;
        }
        for (int s = tid; s < 1024; s += 256)
            ws[s >> 5][s & 31] = W[(kc + (s >> 5)) * 32 + (s & 31)];
        __syncthreads();
#pragma unroll
        for (int k = 0; k < 32; k++) {
            float a[4], b[8];
#pragma unroll
            for (int i = 0; i < 4; i++) a[i] = xs[tr * 4 + i][k];
#pragma unroll
            for (int c = 0; c < 8; c++) b[c] = ws[k][tc * 8 + c];
#pragma unroll
            for (int i = 0; i < 4; i++)
#pragma unroll
                for (int c = 0; c < 8; c++) acc[i][c] += a[i] * b[c];
        }
        __syncthreads();
    }
#pragma unroll
    for (int i = 0; i < 4; i++) {
        int gr = row0 + tr * 4 + i;
        if (gr < N_NODES) {
#pragma unroll
            for (int c = 0; c < 8; c++) g_xw1[(long)gr * 32 + tc * 8 + c] = acc[i][c];
        }
    }
}

// ---------------- GEMM2: hw2 = h @ W2  [100000,32]x[32,40] ----------------
// 256 threads, 256 rows/block, thread tile 4 rows x 10 cols.
__global__ void k_gemm2(const float* __restrict__ W2) {
    __shared__ float xs[256][33];
    __shared__ float ws[32][40];
    int tid = threadIdx.x;
    int row0 = blockIdx.x * 256;
    int tc = tid & 3;     // cols tc*10..+10
    int tr = tid >> 2;    // rows tr*4..+4

    float acc[4][10];
#pragma unroll
    for (int i = 0; i < 4; i++)
#pragma unroll
        for (int c = 0; c < 10; c++) acc[i][c] = 0.f;

    for (int s = tid; s < 2048; s += 256) {
        int r = s >> 3, v = s & 7;
        int gr = row0 + r;
        float4 val = make_float4(0.f, 0.f, 0.f, 0.f);
        if (gr < N_NODES) val = *(const float4*)(g_h + (long)gr * 32 + v * 4);
        xs[r][v * 4 + 0] = val.x;
        xs[r][v * 4 + 1] = val.y;
        xs[r][v * 4 + 2] = val.z;
        xs[r][v * 4 + 3] = val.w;
    }
    for (int s = tid; s < 32 * 40; s += 256) ws[s / 40][s % 40] = W2[s];
    __syncthreads();

#pragma unroll
    for (int k = 0; k < 32; k++) {
        float a[4], b[10];
#pragma unroll
        for (int i = 0; i < 4; i++) a[i] = xs[tr * 4 + i][k];
#pragma unroll
        for (int c = 0; c < 10; c++) b[c] = ws[k][tc * 10 + c];
#pragma unroll
        for (int i = 0; i < 4; i++)
#pragma unroll
            for (int c = 0; c < 10; c++) acc[i][c] += a[i] * b[c];
    }
#pragma unroll
    for (int i = 0; i < 4; i++) {
        int gr = row0 + tr * 4 + i;
        if (gr < N_NODES) {
#pragma unroll
            for (int c = 0; c < 10; c++) g_hw2[(long)gr * 40 + tc * 10 + c] = acc[i][c];
        }
    }
}

// ---------------- gather passes (warp per segment) ----------------
// Layer1 edge gather: e_feat[e] = Binv[e] * sum_{v in e} xw1[v]   (F=32)
__global__ void k_egather1() {
    int w = (blockIdx.x * blockDim.x + threadIdx.x) >> 5;
    int lane = threadIdx.x & 31;
    if (w >= N_EDGES) return;
    int beg = g_eoff[w], end = g_eoff[w + 1];
    float acc = 0.f;
    int i = beg;
    for (; i + 3 < end; i += 4) {
        int v0 = g_edge_members[i + 0];
        int v1 = g_edge_members[i + 1];
        int v2 = g_edge_members[i + 2];
        int v3 = g_edge_members[i + 3];
        float r0 = __ldg(g_xw1 + (long)v0 * 32 + lane);
        float r1 = __ldg(g_xw1 + (long)v1 * 32 + lane);
        float r2 = __ldg(g_xw1 + (long)v2 * 32 + lane);
        float r3 = __ldg(g_xw1 + (long)v3 * 32 + lane);
        acc += r0 + r1 + r2 + r3;
    }
    for (; i < end; i++) acc += __ldg(g_xw1 + (long)g_edge_members[i] * 32 + lane);
    float binv = (end > beg) ? 1.f / (float)(end - beg) : 0.f;
    g_efeat[(long)w * 32 + lane] = acc * binv;
}

// Layer1 node gather + bias + relu: h[v] = relu(Dinv[v]*sum e_feat[e] + b1)
__global__ void k_ngather1(const float* __restrict__ b1) {
    int w = (blockIdx.x * blockDim.x + threadIdx.x) >> 5;
    int lane = threadIdx.x & 31;
    if (w >= N_NODES) return;
    int beg = g_noff[w], end = g_noff[w + 1];
    float acc = 0.f;
    int i = beg;
    for (; i + 3 < end; i += 4) {
        int e0 = g_node_members[i + 0];
        int e1 = g_node_members[i + 1];
        int e2 = g_node_members[i + 2];
        int e3 = g_node_members[i + 3];
        float r0 = __ldg(g_efeat + (long)e0 * 32 + lane);
        float r1 = __ldg(g_efeat + (long)e1 * 32 + lane);
        float r2 = __ldg(g_efeat + (long)e2 * 32 + lane);
        float r3 = __ldg(g_efeat + (long)e3 * 32 + lane);
        acc += r0 + r1 + r2 + r3;
    }
    for (; i < end; i++) acc += __ldg(g_efeat + (long)g_node_members[i] * 32 + lane);
    float dinv = (end > beg) ? 1.f / (float)(end - beg) : 0.f;
    float val = acc * dinv + b1[lane];
    g_h[(long)w * 32 + lane] = fmaxf(val, 0.f);
}

// Layer2 edge gather (F=40): lane handles dims lane and lane+32 (lane<8)
__global__ void k_egather2() {
    int w = (blockIdx.x * blockDim.x + threadIdx.x) >> 5;
    int lane = threadIdx.x & 31;
    if (w >= N_EDGES) return;
    int beg = g_eoff[w], end = g_eoff[w + 1];
    float acc0 = 0.f, acc1 = 0.f;
    int i = beg;
    for (; i + 1 < end; i += 2) {
        int v0 = g_edge_members[i + 0];
        int v1 = g_edge_members[i + 1];
        const float* r0 = g_hw2 + (long)v0 * 40;
        const float* r1 = g_hw2 + (long)v1 * 40;
        acc0 += __ldg(r0 + lane) + __ldg(r1 + lane);
        if (lane < 8) acc1 += __ldg(r0 + 32 + lane) + __ldg(r1 + 32 + lane);
    }
    for (; i < end; i++) {
        const float* r = g_hw2 + (long)g_edge_members[i] * 40;
        acc0 += __ldg(r + lane);
        if (lane < 8) acc1 += __ldg(r + 32 + lane);
    }
    float binv = (end > beg) ? 1.f / (float)(end - beg) : 0.f;
    g_efeat[(long)w * 40 + lane] = acc0 * binv;
    if (lane < 8) g_efeat[(long)w * 40 + 32 + lane] = acc1 * binv;
}

// Layer2 node gather + bias + log_softmax, write final output
__global__ void k_ngather2(const float* __restrict__ b2, float* __restrict__ out) {
    int w = (blockIdx.x * blockDim.x + threadIdx.x) >> 5;
    int lane = threadIdx.x & 31;
    if (w >= N_NODES) return;
    int beg = g_noff[w], end = g_noff[w + 1];
    float acc0 = 0.f, acc1 = 0.f;
    int i = beg;
    for (; i + 1 < end; i += 2) {
        int e0 = g_node_members[i + 0];
        int e1 = g_node_members[i + 1];
        const float* r0 = g_efeat + (long)e0 * 40;
        const float* r1 = g_efeat + (long)e1 * 40;
        acc0 += __ldg(r0 + lane) + __ldg(r1 + lane);
        if (lane < 8) acc1 += __ldg(r0 + 32 + lane) + __ldg(r1 + 32 + lane);
    }
    for (; i < end; i++) {
        const float* r = g_efeat + (long)g_node_members[i] * 40;
        acc0 += __ldg(r + lane);
        if (lane < 8) acc1 += __ldg(r + 32 + lane);
    }
    float dinv = (end > beg) ? 1.f / (float)(end - beg) : 0.f;
    float v0 = acc0 * dinv + b2[lane];
    float v1 = (lane < 8) ? (acc1 * dinv + b2[32 + lane]) : -INFINITY;

    // warp max over 40 valid values
    float m = fmaxf(v0, v1);
#pragma unroll
    for (int d = 16; d > 0; d >>= 1)
        m = fmaxf(m, __shfl_xor_sync(0xFFFFFFFFu, m, d));
    // warp sum of exp
    float s = expf(v0 - m) + ((lane < 8) ? expf(v1 - m) : 0.f);
#pragma unroll
    for (int d = 16; d > 0; d >>= 1)
        s += __shfl_xor_sync(0xFFFFFFFFu, s, d);
    float lz = m + logf(s);

    out[(long)w * 40 + lane] = v0 - lz;
    if (lane < 8) out[(long)w * 40 + 32 + lane] = v1 - lz;
}

// ---------------- launch ----------------
extern "C" void kernel_launch(void* const* d_in, const int* in_sizes, int n_in,
                              void* d_out, int out_size) {
    const float* x    = (const float*)d_in[0];
    const int*   nidx = (const int*)d_in[1];
    const int*   eidx = (const int*)d_in[2];
    const float* W1   = (const float*)d_in[3];
    const float* b1   = (const float*)d_in[4];
    const float* W2   = (const float*)d_in[5];
    const float* b2   = (const float*)d_in[6];
    float* out = (float*)d_out;

    const int TB = 256;
    // CSR build
    k_zero<<<(N_NODES + TB - 1) / TB, TB>>>();
    k_hist<<<(N_INC + TB - 1) / TB, TB>>>(nidx, eidx);
    k_scan<<<2, 1024>>>();
    k_reorder<<<(N_INC + TB - 1) / TB, TB>>>(nidx, eidx);

    // Layer 1
    k_gemm1<<<(N_NODES + 255) / 256, 256>>>(x, W1);
    k_egather1<<<(N_EDGES * 32 + TB - 1) / TB, TB>>>();
    k_ngather1<<<(N_NODES * 32 + TB - 1) / TB, TB>>>(b1);

    // Layer 2
    k_gemm2<<<(N_NODES + 255) / 256, 256>>>(W2);
    k_egather2<<<(N_EDGES * 32 + TB - 1) / TB, TB>>>();
    k_ngather2<<<(N_NODES * 32 + TB - 1) / TB, TB>>>(b2, out);
}

// round 17
// speedup vs baseline: 1.0359x; 1.0359x over previous
#include <cuda_runtime.h>
#include <math.h>

#define N_NODES   100000
#define N_EDGES   50000
#define N_INC     3200000
#define D_IN      128
#define D_HID     32
#define N_CLASSES 40

// ---------------- device scratch (no allocations allowed) ----------------
__device__ int g_ncnt[N_NODES];
__device__ int g_ecnt[N_EDGES];
__device__ int g_noff[N_NODES + 1];
__device__ int g_eoff[N_EDGES + 1];
__device__ int g_ncur[N_NODES];
__device__ int g_ecur[N_EDGES];
__device__ int g_edge_members[N_INC];   // node ids grouped by edge
__device__ int g_node_members[N_INC];   // edge ids grouped by node
__device__ __align__(16) float g_xw1[N_NODES * D_HID];
__device__ __align__(16) float g_efeat[N_EDGES * D_HID];    // 32-dim edge features (both layers)
__device__ __align__(16) float g_h[N_NODES * D_HID];
__device__ __align__(16) float g_agg[N_NODES * D_HID];      // layer-2 aggregated h (pre-W2)

// ---------------- CSR build ----------------
__global__ void k_zero() {
    int i = blockIdx.x * blockDim.x + threadIdx.x;
    if (i < N_NODES) g_ncnt[i] = 0;
    if (i < N_EDGES) g_ecnt[i] = 0;
}

// 4 items per thread, int4 loads -> 4 independent atomic chains (MLP=4)
__global__ void k_hist(const int* __restrict__ nidx, const int* __restrict__ eidx) {
    int i4 = blockIdx.x * blockDim.x + threadIdx.x;
    if (i4 >= N_INC / 4) return;
    int4 vs = ((const int4*)nidx)[i4];
    int4 es = ((const int4*)eidx)[i4];
    atomicAdd(&g_ncnt[vs.x], 1);
    atomicAdd(&g_ncnt[vs.y], 1);
    atomicAdd(&g_ncnt[vs.z], 1);
    atomicAdd(&g_ncnt[vs.w], 1);
    atomicAdd(&g_ecnt[es.x], 1);
    atomicAdd(&g_ecnt[es.y], 1);
    atomicAdd(&g_ecnt[es.z], 1);
    atomicAdd(&g_ecnt[es.w], 1);
}

// Exclusive scan with warp-shuffle block scan.
// block 0: node counts -> g_noff + g_ncur;  block 1: edge counts -> g_eoff + g_ecur.
__global__ void k_scan() {
    const int* cnt;
    int* off;
    int* cur;
    int n;
    if (blockIdx.x == 0) { cnt = g_ncnt; off = g_noff; cur = g_ncur; n = N_NODES; }
    else                 { cnt = g_ecnt; off = g_eoff; cur = g_ecur; n = N_EDGES; }

    __shared__ int warp_sums[32];
    int tid = threadIdx.x;
    int lane = tid & 31;
    int wid = tid >> 5;
    int carry = 0;

    for (int base = 0; base < n; base += 1024) {
        int idx = base + tid;
        int v = (idx < n) ? cnt[idx] : 0;

        int x = v;
#pragma unroll
        for (int d = 1; d < 32; d <<= 1) {
            int t = __shfl_up_sync(0xFFFFFFFFu, x, d);
            if (lane >= d) x += t;
        }
        if (lane == 31) warp_sums[wid] = x;
        __syncthreads();

        if (wid == 0) {
            int s = warp_sums[lane];
#pragma unroll
            for (int d = 1; d < 32; d <<= 1) {
                int t = __shfl_up_sync(0xFFFFFFFFu, s, d);
                if (lane >= d) s += t;
            }
            warp_sums[lane] = s;
        }
        __syncthreads();

        int prefix = (wid > 0) ? warp_sums[wid - 1] : 0;
        int excl = carry + prefix + x - v;
        if (idx < n) {
            off[idx] = excl;
            cur[idx] = excl;
        }
        int total = warp_sums[31];
        __syncthreads();
        carry += total;
    }
    if (tid == 0) off[n] = carry;
}

// 4 items per thread -> 4 independent atomic->store chains
__global__ void k_reorder(const int* __restrict__ nidx, const int* __restrict__ eidx) {
    int i4 = blockIdx.x * blockDim.x + threadIdx.x;
    if (i4 >= N_INC / 4) return;
    int4 vs = ((const int4*)nidx)[i4];
    int4 es = ((const int4*)eidx)[i4];

    int p0 = atomicAdd(&g_ecur[es.x], 1);
    int p1 = atomicAdd(&g_ecur[es.y], 1);
    int p2 = atomicAdd(&g_ecur[es.z], 1);
    int p3 = atomicAdd(&g_ecur[es.w], 1);
    g_edge_members[p0] = vs.x;
    g_edge_members[p1] = vs.y;
    g_edge_members[p2] = vs.z;
    g_edge_members[p3] = vs.w;

    int q0 = atomicAdd(&g_ncur[vs.x], 1);
    int q1 = atomicAdd(&g_ncur[vs.y], 1);
    int q2 = atomicAdd(&g_ncur[vs.z], 1);
    int q3 = atomicAdd(&g_ncur[vs.w], 1);
    g_node_members[q0] = es.x;
    g_node_members[q1] = es.y;
    g_node_members[q2] = es.z;
    g_node_members[q3] = es.w;
}

// ---------------- GEMM1: xw1 = x @ W1  [100000,128]x[128,32] ----------------
__global__ void k_gemm1(const float* __restrict__ X, const float* __restrict__ W) {
    __shared__ float xs[256][33];
    __shared__ float ws[32][32];
    int tid = threadIdx.x;
    int row0 = blockIdx.x * 256;
    int tc = tid & 3;
    int tr = tid >> 2;

    float acc[4][8];
#pragma unroll
    for (int i = 0; i < 4; i++)
#pragma unroll
        for (int c = 0; c < 8; c++) acc[i][c] = 0.f;

    for (int kc = 0; kc < 128; kc += 32) {
        for (int s = tid; s < 2048; s += 256) {
            int r = s >> 3, v = s & 7;
            int gr = row0 + r;
            float4 val = make_float4(0.f, 0.f, 0.f, 0.f);
            if (gr < N_NODES) val = *(const float4*)(X + (long)gr * 128 + kc + v * 4);
            xs[r][v * 4 + 0] = val.x;
            xs[r][v * 4 + 1] = val.y;
            xs[r][v * 4 + 2] = val.z;
            xs[r][v * 4 + 3] = val.w;
        }
        for (int s = tid; s < 1024; s += 256)
            ws[s >> 5][s & 31] = W[(kc + (s >> 5)) * 32 + (s & 31)];
        __syncthreads();
#pragma unroll
        for (int k = 0; k < 32; k++) {
            float a[4], b[8];
#pragma unroll
            for (int i = 0; i < 4; i++) a[i] = xs[tr * 4 + i][k];
#pragma unroll
            for (int c = 0; c < 8; c++) b[c] = ws[k][tc * 8 + c];
#pragma unroll
            for (int i = 0; i < 4; i++)
#pragma unroll
                for (int c = 0; c < 8; c++) acc[i][c] += a[i] * b[c];
        }
        __syncthreads();
    }
#pragma unroll
    for (int i = 0; i < 4; i++) {
        int gr = row0 + tr * 4 + i;
        if (gr < N_NODES) {
#pragma unroll
            for (int c = 0; c < 8; c++) g_xw1[(long)gr * 32 + tc * 8 + c] = acc[i][c];
        }
    }
}

// ---------------- gather passes (warp per segment, 32-dim rows) ----------------
// Buffers bound at COMPILE TIME inside device code — device-global symbols must
// never be passed as kernel arguments from host (host shadow address + GB300 ATS
// silently reads host memory).

// layer1 edge gather: e_feat[e] = Binv[e] * sum_{v in e} xw1[v]
__global__ void k_egather1() {
    int w = (blockIdx.x * blockDim.x + threadIdx.x) >> 5;
    int lane = threadIdx.x & 31;
    if (w >= N_EDGES) return;
    int beg = g_eoff[w], end = g_eoff[w + 1];
    float acc = 0.f;
    int i = beg;
    for (; i + 3 < end; i += 4) {
        int v0 = g_edge_members[i + 0];
        int v1 = g_edge_members[i + 1];
        int v2 = g_edge_members[i + 2];
        int v3 = g_edge_members[i + 3];
        float r0 = __ldg(g_xw1 + (long)v0 * 32 + lane);
        float r1 = __ldg(g_xw1 + (long)v1 * 32 + lane);
        float r2 = __ldg(g_xw1 + (long)v2 * 32 + lane);
        float r3 = __ldg(g_xw1 + (long)v3 * 32 + lane);
        acc += r0 + r1 + r2 + r3;
    }
    for (; i < end; i++) acc += __ldg(g_xw1 + (long)g_edge_members[i] * 32 + lane);
    float binv = (end > beg) ? 1.f / (float)(end - beg) : 0.f;
    g_efeat[(long)w * 32 + lane] = acc * binv;
}

// layer1 node gather: h[v] = relu(Dinv[v]*sum e_feat[e] + b1)
__global__ void k_ngather1(const float* __restrict__ b1) {
    int w = (blockIdx.x * blockDim.x + threadIdx.x) >> 5;
    int lane = threadIdx.x & 31;
    if (w >= N_NODES) return;
    int beg = g_noff[w], end = g_noff[w + 1];
    float acc = 0.f;
    int i = beg;
    for (; i + 3 < end; i += 4) {
        int e0 = g_node_members[i + 0];
        int e1 = g_node_members[i + 1];
        int e2 = g_node_members[i + 2];
        int e3 = g_node_members[i + 3];
        float r0 = __ldg(g_efeat + (long)e0 * 32 + lane);
        float r1 = __ldg(g_efeat + (long)e1 * 32 + lane);
        float r2 = __ldg(g_efeat + (long)e2 * 32 + lane);
        float r3 = __ldg(g_efeat + (long)e3 * 32 + lane);
        acc += r0 + r1 + r2 + r3;
    }
    for (; i < end; i++) acc += __ldg(g_efeat + (long)g_node_members[i] * 32 + lane);
    float dinv = (end > beg) ? 1.f / (float)(end - beg) : 0.f;
    float val = acc * dinv + b1[lane];
    g_h[(long)w * 32 + lane] = fmaxf(val, 0.f);
}

// layer2 edge gather: e_feat[e] = Binv[e] * sum_{v in e} h[v]
__global__ void k_egather2() {
    int w = (blockIdx.x * blockDim.x + threadIdx.x) >> 5;
    int lane = threadIdx.x & 31;
    if (w >= N_EDGES) return;
    int beg = g_eoff[w], end = g_eoff[w + 1];
    float acc = 0.f;
    int i = beg;
    for (; i + 3 < end; i += 4) {
        int v0 = g_edge_members[i + 0];
        int v1 = g_edge_members[i + 1];
        int v2 = g_edge_members[i + 2];
        int v3 = g_edge_members[i + 3];
        float r0 = __ldg(g_h + (long)v0 * 32 + lane);
        float r1 = __ldg(g_h + (long)v1 * 32 + lane);
        float r2 = __ldg(g_h + (long)v2 * 32 + lane);
        float r3 = __ldg(g_h + (long)v3 * 32 + lane);
        acc += r0 + r1 + r2 + r3;
    }
    for (; i < end; i++) acc += __ldg(g_h + (long)g_edge_members[i] * 32 + lane);
    float binv = (end > beg) ? 1.f / (float)(end - beg) : 0.f;
    g_efeat[(long)w * 32 + lane] = acc * binv;
}

// layer2 node gather: agg[v] = Dinv[v]*sum e_feat[e]   (pre-W2; linearity of conv)
__global__ void k_ngather2() {
    int w = (blockIdx.x * blockDim.x + threadIdx.x) >> 5;
    int lane = threadIdx.x & 31;
    if (w >= N_NODES) return;
    int beg = g_noff[w], end = g_noff[w + 1];
    float acc = 0.f;
    int i = beg;
    for (; i + 3 < end; i += 4) {
        int e0 = g_node_members[i + 0];
        int e1 = g_node_members[i + 1];
        int e2 = g_node_members[i + 2];
        int e3 = g_node_members[i + 3];
        float r0 = __ldg(g_efeat + (long)e0 * 32 + lane);
        float r1 = __ldg(g_efeat + (long)e1 * 32 + lane);
        float r2 = __ldg(g_efeat + (long)e2 * 32 + lane);
        float r3 = __ldg(g_efeat + (long)e3 * 32 + lane);
        acc += r0 + r1 + r2 + r3;
    }
    for (; i < end; i++) acc += __ldg(g_efeat + (long)g_node_members[i] * 32 + lane);
    float dinv = (end > beg) ? 1.f / (float)(end - beg) : 0.f;
    g_agg[(long)w * 32 + lane] = acc * dinv;
}

// ---------------- fused output: out = log_softmax(agg @ W2 + b2) ----------------
// warp per node; W2 (32x40) and b2 staged in shared.
__global__ void k_out(const float* __restrict__ W2, const float* __restrict__ b2,
                      float* __restrict__ out) {
    __shared__ float sW[32][40];
    __shared__ float sb[40];
    int tid = threadIdx.x;
    for (int s = tid; s < 32 * 40; s += 256) sW[s / 40][s % 40] = W2[s];
    if (tid < 40) sb[tid] = b2[tid];
    __syncthreads();

    int w = (blockIdx.x * blockDim.x + tid) >> 5;
    int lane = tid & 31;
    if (w >= N_NODES) return;

    float a = g_agg[(long)w * 32 + lane];
    float t0 = 0.f, t1 = 0.f;
#pragma unroll
    for (int k = 0; k < 32; k++) {
        float ak = __shfl_sync(0xFFFFFFFFu, a, k);
        t0 += ak * sW[k][lane];
        if (lane < 8) t1 += ak * sW[k][32 + lane];
    }
    float v0 = t0 + sb[lane];
    float v1 = (lane < 8) ? (t1 + sb[32 + lane]) : -INFINITY;

    // warp max over 40 valid values
    float m = fmaxf(v0, v1);
#pragma unroll
    for (int d = 16; d > 0; d >>= 1)
        m = fmaxf(m, __shfl_xor_sync(0xFFFFFFFFu, m, d));
    // warp sum of exp
    float s = expf(v0 - m) + ((lane < 8) ? expf(v1 - m) : 0.f);
#pragma unroll
    for (int d = 16; d > 0; d >>= 1)
        s += __shfl_xor_sync(0xFFFFFFFFu, s, d);
    float lz = m + logf(s);

    out[(long)w * 40 + lane] = v0 - lz;
    if (lane < 8) out[(long)w * 40 + 32 + lane] = v1 - lz;
}

// ---------------- launch ----------------
extern "C" void kernel_launch(void* const* d_in, const int* in_sizes, int n_in,
                              void* d_out, int out_size) {
    const float* x    = (const float*)d_in[0];
    const int*   nidx = (const int*)d_in[1];
    const int*   eidx = (const int*)d_in[2];
    const float* W1   = (const float*)d_in[3];
    const float* b1   = (const float*)d_in[4];
    const float* W2   = (const float*)d_in[5];
    const float* b2   = (const float*)d_in[6];
    float* out = (float*)d_out;

    const int TB = 256;
    // CSR build
    k_zero<<<(N_NODES + TB - 1) / TB, TB>>>();
    k_hist<<<(N_INC / 4 + TB - 1) / TB, TB>>>(nidx, eidx);
    k_scan<<<2, 1024>>>();
    k_reorder<<<(N_INC / 4 + TB - 1) / TB, TB>>>(nidx, eidx);

    // Layer 1
    k_gemm1<<<(N_NODES + 255) / 256, 256>>>(x, W1);
    k_egather1<<<(N_EDGES * 32 + TB - 1) / TB, TB>>>();
    k_ngather1<<<(N_NODES * 32 + TB - 1) / TB, TB>>>(b1);

    // Layer 2 (aggregate 32-dim h first; W2 applied in fused epilogue)
    k_egather2<<<(N_EDGES * 32 + TB - 1) / TB, TB>>>();
    k_ngather2<<<(N_NODES * 32 + TB - 1) / TB, TB>>>();
    k_out<<<(N_NODES * 32 + TB - 1) / TB, TB>>>(W2, b2, out);
}